// round 3
// baseline (speedup 1.0000x reference)
#include <cuda_runtime.h>
#include <math.h>

#define BB 32
#define CC 16
#define HH 256
#define WW 256
#define NOBJ 16
#define HW (HH*WW)

// Zero-initialized at module load; the last finishing block resets them after
// producing the output, so every graph replay sees zeroed state.
__device__ double   g_base_sum;
__device__ double   g_spatial_sum;
__device__ int      g_count[BB];
__device__ unsigned g_done;

// grid: (HW/(4*256), BB) = (64, 32), block: 256 threads.
// Each thread: 4 consecutive pixels (one float4 per channel per tensor).
__global__ void __launch_bounds__(256, 2)
scl_fused_kernel(const float* __restrict__ pred,
                 const float* __restrict__ targ,
                 const float* __restrict__ layout,
                 const float* __restrict__ obj_counts,
                 float* __restrict__ out)
{
    const int b = blockIdx.y;

    __shared__ int sxs[NOBJ], sxe[NOBJ], sys[NOBJ], sye[NOBJ];
    if (threadIdx.x < NOBJ) {
        const float* L = layout + ((size_t)b * NOBJ + threadIdx.x) * 4;
        float x = L[0], y = L[1], w = L[2], h = L[3];
        bool valid = (x > 0.0f) && (y > 0.0f);
        int xs = (int)floorf(x * WW);
        int ys = (int)floorf(y * HH);
        int xe = (int)floorf((x + w) * WW);
        int ye = (int)floorf((y + h) * HH);
        if (!valid) { xs = 0; xe = 0; ys = 0; ye = 0; }
        sxs[threadIdx.x] = xs; sxe[threadIdx.x] = xe;
        sys[threadIdx.x] = ys; sye[threadIdx.x] = ye;
    }
    __syncthreads();

    const int pix4    = blockIdx.x * blockDim.x + threadIdx.x;
    const int basepix = pix4 * 4;
    const int hrow    = basepix / WW;
    const int wcol0   = basepix % WW;

    const size_t off0 = (size_t)b * CC * HW + basepix;

    float acc_sq = 0.0f;
    float a0 = 0.0f, a1 = 0.0f, a2 = 0.0f, a3 = 0.0f;

    // Chunked front-batching: 16 LDG.128 in flight per chunk (64 regs of data),
    // two chunks. Fits the 128-reg budget without spills.
#pragma unroll
    for (int cc0 = 0; cc0 < CC; cc0 += 8) {
        float4 pv[8], tv[8];
#pragma unroll
        for (int j = 0; j < 8; ++j)
            pv[j] = __ldg((const float4*)(pred + off0 + (size_t)(cc0 + j) * HW));
#pragma unroll
        for (int j = 0; j < 8; ++j)
            tv[j] = __ldg((const float4*)(targ + off0 + (size_t)(cc0 + j) * HW));
#pragma unroll
        for (int j = 0; j < 8; ++j) {
            float d0 = pv[j].x - tv[j].x;
            float d1 = pv[j].y - tv[j].y;
            float d2 = pv[j].z - tv[j].z;
            float d3 = pv[j].w - tv[j].w;
            acc_sq = fmaf(d0, d0, acc_sq);
            acc_sq = fmaf(d1, d1, acc_sq);
            acc_sq = fmaf(d2, d2, acc_sq);
            acc_sq = fmaf(d3, d3, acc_sq);
            a0 += fabsf(pv[j].x);
            a1 += fabsf(pv[j].y);
            a2 += fabsf(pv[j].z);
            a3 += fabsf(pv[j].w);
        }
    }

    // Per-row object hit mask (same h for all 4 pixels)
    unsigned rowmask = 0u;
#pragma unroll
    for (int o = 0; o < NOBJ; ++o) {
        if (hrow >= sys[o] && hrow < sye[o]) rowmask |= (1u << o);
    }

    float sa[4] = { a0 * (1.0f/16.0f), a1 * (1.0f/16.0f),
                    a2 * (1.0f/16.0f), a3 * (1.0f/16.0f) };

    float acc_sp = 0.0f;
    int   cnt    = 0;
#pragma unroll
    for (int i = 0; i < 4; ++i) {
        const int wc = wcol0 + i;
        bool cov = false;
        unsigned m = rowmask;
        while (m) {
            int o = __ffs(m) - 1;
            m &= m - 1;
            if (wc >= sxs[o] && wc < sxe[o]) { cov = true; break; }
        }
        float ts = cov ? 1.0f : 0.0f;
        float d  = sa[i] - ts;
        acc_sp = fmaf(d, d, acc_sp);
        cnt += (sa[i] > 0.5f) ? 1 : 0;
    }

    // ---- block reduction ----
    const unsigned FULL = 0xFFFFFFFFu;
#pragma unroll
    for (int s = 16; s > 0; s >>= 1) {
        acc_sq += __shfl_down_sync(FULL, acc_sq, s);
        acc_sp += __shfl_down_sync(FULL, acc_sp, s);
        cnt    += __shfl_down_sync(FULL, cnt,    s);
    }

    __shared__ float s_sq[8], s_sp[8];
    __shared__ int   s_ct[8];
    const int lane = threadIdx.x & 31;
    const int wid  = threadIdx.x >> 5;
    if (lane == 0) { s_sq[wid] = acc_sq; s_sp[wid] = acc_sp; s_ct[wid] = cnt; }
    __syncthreads();

    if (wid == 0 && lane == 0) {
        float bsq = 0.0f, bsp = 0.0f;
        int   bct = 0;
#pragma unroll
        for (int i = 0; i < 8; ++i) { bsq += s_sq[i]; bsp += s_sp[i]; bct += s_ct[i]; }
        atomicAdd(&g_base_sum,    (double)bsq);
        atomicAdd(&g_spatial_sum, (double)bsp);
        atomicAdd(&g_count[b],    bct);
    }

    // ---- last-block finalize + reset ----
    __shared__ unsigned s_ticket;
    if (threadIdx.x == 0) {
        __threadfence();
        s_ticket = atomicAdd(&g_done, 1u);
    }
    __syncthreads();

    const unsigned total = gridDim.x * gridDim.y;
    if (s_ticket == total - 1u && threadIdx.x == 0) {
        __threadfence();
        volatile double* vbase = &g_base_sum;
        volatile double* vspat = &g_spatial_sum;
        double bsum = *vbase;
        double ssum = *vspat;

        float csum = 0.0f;
#pragma unroll
        for (int i = 0; i < BB; ++i) {
            volatile int* vc = &g_count[i];
            float d = (float)(*vc) - obj_counts[i];
            csum = fmaf(d, d, csum);
        }

        double base_loss    = bsum / ((double)BB * CC * HH * WW);
        double spatial_loss = ssum / ((double)BB * HH * WW);
        double count_loss   = (double)csum / (double)BB;
        out[0] = (float)(base_loss + spatial_loss + 0.5 * count_loss);

        // Reset for the next replay.
        g_base_sum    = 0.0;
        g_spatial_sum = 0.0;
#pragma unroll
        for (int i = 0; i < BB; ++i) g_count[i] = 0;
        __threadfence();
        g_done = 0u;
    }
}

extern "C" void kernel_launch(void* const* d_in, const int* in_sizes, int n_in,
                              void* d_out, int out_size)
{
    const float* pred   = (const float*)d_in[0];
    const float* targ   = (const float*)d_in[1];
    const float* layout = (const float*)d_in[2];
    const float* ocnt   = (const float*)d_in[3];
    float* out = (float*)d_out;

    dim3 grid(HW / (4 * 256), BB);
    scl_fused_kernel<<<grid, 256>>>(pred, targ, layout, ocnt, out);
}

// round 6
// speedup vs baseline: 1.0039x; 1.0039x over previous
#include <cuda_runtime.h>
#include <math.h>

#define BB 32
#define CC 16
#define HH 256
#define WW 256
#define NOBJ 16
#define HW (HH*WW)

// Zero-initialized at module load; the last finishing block resets them after
// producing the output, so every graph replay sees zeroed state.
__device__ double   g_base_sum;
__device__ double   g_spatial_sum;
__device__ int      g_count[BB];
__device__ unsigned g_done;

// grid: (HW/(4*256), BB) = (64, 32), block: 256 threads.
// Each thread: 4 consecutive pixels (one float4 per channel per tensor).
__global__ void __launch_bounds__(256, 4)
scl_fused_kernel(const float* __restrict__ pred,
                 const float* __restrict__ targ,
                 const float* __restrict__ layout,
                 const float* __restrict__ obj_counts,
                 float* __restrict__ out)
{
    const int b = blockIdx.y;

    __shared__ int sxs[NOBJ], sxe[NOBJ], sys[NOBJ], sye[NOBJ];
    if (threadIdx.x < NOBJ) {
        const float* L = layout + ((size_t)b * NOBJ + threadIdx.x) * 4;
        float x = L[0], y = L[1], w = L[2], h = L[3];
        bool valid = (x > 0.0f) && (y > 0.0f);
        int xs = (int)floorf(x * WW);
        int ys = (int)floorf(y * HH);
        int xe = (int)floorf((x + w) * WW);
        int ye = (int)floorf((y + h) * HH);
        if (!valid) { xs = 0; xe = 0; ys = 0; ye = 0; }
        sxs[threadIdx.x] = xs; sxe[threadIdx.x] = xe;
        sys[threadIdx.x] = ys; sye[threadIdx.x] = ye;
    }
    __syncthreads();

    const int pix4    = blockIdx.x * blockDim.x + threadIdx.x;
    const int basepix = pix4 * 4;
    const int hrow    = basepix / WW;
    const int wcol0   = basepix % WW;

    const size_t off0 = (size_t)b * CC * HW + basepix;

    float acc_sq = 0.0f;
    float a0 = 0.0f, a1 = 0.0f, a2 = 0.0f, a3 = 0.0f;

    // Interleaved load/compute; full unroll lets ptxas keep many LDG.128
    // in flight while staying within the 64-reg / 4-CTA occupancy budget.
#pragma unroll
    for (int c = 0; c < CC; ++c) {
        float4 pv = __ldg((const float4*)(pred + off0 + (size_t)c * HW));
        float4 tv = __ldg((const float4*)(targ + off0 + (size_t)c * HW));
        float d0 = pv.x - tv.x;
        float d1 = pv.y - tv.y;
        float d2 = pv.z - tv.z;
        float d3 = pv.w - tv.w;
        acc_sq = fmaf(d0, d0, acc_sq);
        acc_sq = fmaf(d1, d1, acc_sq);
        acc_sq = fmaf(d2, d2, acc_sq);
        acc_sq = fmaf(d3, d3, acc_sq);
        a0 += fabsf(pv.x);
        a1 += fabsf(pv.y);
        a2 += fabsf(pv.z);
        a3 += fabsf(pv.w);
    }

    // Per-row object hit mask (same h for all 4 pixels)
    unsigned rowmask = 0u;
#pragma unroll
    for (int o = 0; o < NOBJ; ++o) {
        if (hrow >= sys[o] && hrow < sye[o]) rowmask |= (1u << o);
    }

    float sa[4] = { a0 * (1.0f/16.0f), a1 * (1.0f/16.0f),
                    a2 * (1.0f/16.0f), a3 * (1.0f/16.0f) };

    float acc_sp = 0.0f;
    int   cnt    = 0;
#pragma unroll
    for (int i = 0; i < 4; ++i) {
        const int wc = wcol0 + i;
        bool cov = false;
        unsigned m = rowmask;
        while (m) {
            int o = __ffs(m) - 1;
            m &= m - 1;
            if (wc >= sxs[o] && wc < sxe[o]) { cov = true; break; }
        }
        float ts = cov ? 1.0f : 0.0f;
        float d  = sa[i] - ts;
        acc_sp = fmaf(d, d, acc_sp);
        cnt += (sa[i] > 0.5f) ? 1 : 0;
    }

    // ---- block reduction ----
    const unsigned FULL = 0xFFFFFFFFu;
#pragma unroll
    for (int s = 16; s > 0; s >>= 1) {
        acc_sq += __shfl_down_sync(FULL, acc_sq, s);
        acc_sp += __shfl_down_sync(FULL, acc_sp, s);
        cnt    += __shfl_down_sync(FULL, cnt,    s);
    }

    __shared__ float s_sq[8], s_sp[8];
    __shared__ int   s_ct[8];
    const int lane = threadIdx.x & 31;
    const int wid  = threadIdx.x >> 5;
    if (lane == 0) { s_sq[wid] = acc_sq; s_sp[wid] = acc_sp; s_ct[wid] = cnt; }
    __syncthreads();

    if (wid == 0 && lane == 0) {
        float bsq = 0.0f, bsp = 0.0f;
        int   bct = 0;
#pragma unroll
        for (int i = 0; i < 8; ++i) { bsq += s_sq[i]; bsp += s_sp[i]; bct += s_ct[i]; }
        atomicAdd(&g_base_sum,    (double)bsq);
        atomicAdd(&g_spatial_sum, (double)bsp);
        atomicAdd(&g_count[b],    bct);
    }

    // ---- last-block finalize + reset ----
    __shared__ unsigned s_ticket;
    if (threadIdx.x == 0) {
        __threadfence();
        s_ticket = atomicAdd(&g_done, 1u);
    }
    __syncthreads();

    const unsigned total = gridDim.x * gridDim.y;
    if (s_ticket == total - 1u && threadIdx.x == 0) {
        __threadfence();
        volatile double* vbase = &g_base_sum;
        volatile double* vspat = &g_spatial_sum;
        double bsum = *vbase;
        double ssum = *vspat;

        float csum = 0.0f;
#pragma unroll
        for (int i = 0; i < BB; ++i) {
            volatile int* vc = &g_count[i];
            float d = (float)(*vc) - obj_counts[i];
            csum = fmaf(d, d, csum);
        }

        double base_loss    = bsum / ((double)BB * CC * HH * WW);
        double spatial_loss = ssum / ((double)BB * HH * WW);
        double count_loss   = (double)csum / (double)BB;
        out[0] = (float)(base_loss + spatial_loss + 0.5 * count_loss);

        // Reset for the next replay.
        g_base_sum    = 0.0;
        g_spatial_sum = 0.0;
#pragma unroll
        for (int i = 0; i < BB; ++i) g_count[i] = 0;
        __threadfence();
        g_done = 0u;
    }
}

extern "C" void kernel_launch(void* const* d_in, const int* in_sizes, int n_in,
                              void* d_out, int out_size)
{
    const float* pred   = (const float*)d_in[0];
    const float* targ   = (const float*)d_in[1];
    const float* layout = (const float*)d_in[2];
    const float* ocnt   = (const float*)d_in[3];
    float* out = (float*)d_out;

    dim3 grid(HW / (4 * 256), BB);
    scl_fused_kernel<<<grid, 256>>>(pred, targ, layout, ocnt, out);
}